// round 14
// baseline (speedup 1.0000x reference)
#include <cuda_runtime.h>
#include <cuda_bf16.h>
#include <math.h>

#define B 128
#define T 1024
#define H 256
#define KS 18     // bf16 k16 MMA k-steps: K = 288 = 256 h + 20 loc/bias + 12 pad

// ------------------- device scratch (static) -------------------
__device__ float    g_loc[(size_t)T * B * 20];       // [t][b][20]: loc_dense(16) + td(3) + 1.0
__device__ float    g_hstore[(size_t)2 * T * B * H]; // recorded h (fp32), [d][t][b][h]
__device__ unsigned g_WB[2 * 8 * 8 * KS * 32 * 4];   // fused [Whh|Wih|b] bf16 A-frags (bf16x2/u32)
__device__ float    g_outWT[512 * 32];               // out_W transposed: [k][j]
__device__ float    g_af[B * 32];                    // addr_feat
__device__ float    g_scores[B * T];

__device__ __forceinline__ float tanh_fast(float x) {
    float r;
    asm("tanh.approx.f32 %0, %1;" : "=f"(r) : "f"(x));
    return r;
}
__device__ __forceinline__ float sigm(float x) {
    return fmaf(0.5f, tanh_fast(0.5f * x), 0.5f);
}
__device__ __forceinline__ void mma_bf16(float c[4], uint4 a, unsigned b0, unsigned b1) {
    asm volatile("mma.sync.aligned.m16n8k16.row.col.f32.bf16.bf16.f32 "
                 "{%0,%1,%2,%3}, {%4,%5,%6,%7}, {%8,%9}, {%0,%1,%2,%3};"
                 : "+f"(c[0]), "+f"(c[1]), "+f"(c[2]), "+f"(c[3])
                 : "r"(a.x), "r"(a.y), "r"(a.z), "r"(a.w), "r"(b0), "r"(b1));
}
__device__ __forceinline__ unsigned pack_bf16x2(float lo, float hi) {
    unsigned u;
    asm("cvt.rn.bf16x2.f32 %0, %1, %2;" : "=r"(u) : "f"(hi), "f"(lo));
    return u;
}

// smem layout (bytes)
#define WF_BYTES  73728                  // 8 m x 18 ks x 32 lane x 4 u32
#define HROW      148                    // u32 per B row (296 bf16; (20g+t)%32 distinct -> conflict-free)
#define HT_BYTES  (16 * HROW * 4)        // 9472
#define OFF_HT0   WF_BYTES
#define OFF_HT1   (OFF_HT0 + HT_BYTES)
#define OFF_PRE   (OFF_HT1 + HT_BYTES)
#define OFF_MBAR  (OFF_PRE + 128 * 20 * 4)
#define LSTM_SMEM 118784                 // padded so each CTA owns an SM

// ------------------- weight prep: fused bf16 A-fragments + outWT -------------------
__global__ void prep_kernel(const float* __restrict__ Whh_f, const float* __restrict__ Whh_b,
                            const float* __restrict__ Wih_f, const float* __restrict__ b_f,
                            const float* __restrict__ Wih_b, const float* __restrict__ b_b,
                            const float* __restrict__ out_W) {
    int idx = blockIdx.x * 256 + threadIdx.x;
    if (idx < 2 * 8 * 8 * KS * 32 * 4) {
        int r     = idx & 3;
        int lane  = (idx >> 2) & 31;
        int ks    = (idx >> 7) % KS;
        int rest  = (idx >> 7) / KS;
        int m     = rest & 7;
        int gxp   = (rest >> 3) & 7;
        int d     = rest >> 6;
        int g = lane >> 2, t = lane & 3;
        int row_local = g + (r & 1) * 8;
        int kbase = ks * 16 + 2 * t + ((r & 2) ? 8 : 0);
        int rp = gxp * 128 + m * 16 + row_local;   // reordered row r' = 4*jh + gate
        int gate = rp & 3, jh = rp >> 2;
        int orig = gate * 256 + jh;
        float v[2];
        #pragma unroll
        for (int q = 0; q < 2; q++) {
            int k = kbase + q;
            if (k < 256)            v[q] = (d ? Whh_b : Whh_f)[orig * H + k];
            else if (k < 275)       v[q] = (d ? Wih_b : Wih_f)[orig * 19 + (k - 256)];
            else if (k == 275)      v[q] = (d ? b_b : b_f)[orig];
            else                    v[q] = 0.0f;
        }
        g_WB[idx] = pack_bf16x2(v[0], v[1]);
    }
    if (idx < 512 * 32) {
        int k = idx >> 5, j = idx & 31;
        g_outWT[idx] = out_W[j * 512 + k];
    }
}

// ------------------- addr_feat -------------------
__global__ void addr_kernel(const float* __restrict__ addr,
                            const int*   __restrict__ addr_type,
                            const float* __restrict__ poi_emb,
                            const float* __restrict__ addr_W,
                            const float* __restrict__ addr_b) {
    int b = threadIdx.x;  // 128
    float inp[4];
    inp[0] = addr[b];
    int at = addr_type[b];
    inp[1] = poi_emb[at * 3 + 0];
    inp[2] = poi_emb[at * 3 + 1];
    inp[3] = poi_emb[at * 3 + 2];
    for (int j = 0; j < 32; j++) {
        float a = addr_b[j];
        #pragma unroll
        for (int f = 0; f < 4; f++) a += addr_W[j * 4 + f] * inp[f];
        g_af[b * 32 + j] = a;
    }
}

// ------------------- loc_kernel: g_loc[t][b][20] = [loc_dense | td | 1], active only -------------------
__global__ void __launch_bounds__(320) loc_kernel(
    const float* __restrict__ loc_dense, const float* __restrict__ time_dist,
    const int* __restrict__ len, const float* __restrict__ time_W,
    const float* __restrict__ time_b) {
    int b = blockIdx.y;
    int t0 = blockIdx.x * 16;
    int n = len[b];
    if (t0 >= n) return;
    int tid = threadIdx.x;
    int tt = tid / 20, e = tid - tt * 20;
    int t = t0 + tt;
    if (t >= n) return;
    float v;
    if (e < 16) {
        v = loc_dense[((size_t)b * T + t) * 16 + e];
    } else if (e < 19) {
        int w = e - 16;
        float acc = time_b[w];
        const float* tdp = &time_dist[((size_t)b * T + t) * 8];
        #pragma unroll
        for (int f = 0; f < 8; f++) acc += time_W[w * 8 + f] * tdp[f];
        v = acc;
    } else {
        v = 1.0f;   // bias lane
    }
    g_loc[((size_t)t * B + b) * 20 + e] = v;
}

// ------------------- persistent bidirectional LSTM: fused-K bf16 MMA + mbarrier DSMEM sync ------------
// Grid (8,8,2), cluster (8,1,1) = 8 gate-tile CTAs sharing (btile, dir).
// gates[128 rows][16 b] = [Whh|Wih|b] (bf16 A frags) x [h; loc; 1] (bf16 B rows, u32-packed pairs).
// K = 288: k<256 = h (DSMEM-exchanged as bf16x2 u32), k 256..275 = loc+bias, rest zero pad.
// Exchange: shuffle-pair pack, even threads issue 8 remote u32 stores (2048/CTA/step).
// Sync identical to R10/R13: 2 block syncs, count=8 double-buffered mbarriers, tids 0-7 arrive.
__global__ void __launch_bounds__(512, 1) __cluster_dims__(8, 1, 1)
lstm_kernel(const int* __restrict__ len) {
    extern __shared__ __align__(16) unsigned char smem[];
    float* pre = (float*)(smem + OFF_PRE);           // [128 rows][20 b]

    int gx  = blockIdx.x;   // gate tile == cluster rank
    int gy  = blockIdx.y;
    int dir = blockIdx.z;
    int tid = threadIdx.x;
    int b0  = gy * 16;
    int nloc = len[b0];     // sorted descending -> tile max (same for whole cluster)

    unsigned mbar_local;
    asm("{ .reg .u64 tt; cvta.to.shared.u64 tt, %1; cvt.u32.u64 %0, tt; }"
        : "=r"(mbar_local) : "l"((void*)(smem + OFF_MBAR)));

    // resident fused weight fragments (72 KB)
    {
        const uint4* Wf = reinterpret_cast<const uint4*>(g_WB) + (size_t)(dir * 8 + gx) * 4608;
        uint4* dst = reinterpret_cast<uint4*>(smem);
        for (int e = tid; e < 4608; e += 512) dst[e] = Wf[e];
    }
    // zero BOTH h buffers (incl. pad k-region, never rewritten)
    for (int e = tid; e < 2 * HT_BYTES / 4; e += 512) ((unsigned*)(smem + OFF_HT0))[e] = 0u;
    if (tid == 0) {
        asm volatile("mbarrier.init.shared.b64 [%0], %1;" :: "r"(mbar_local), "r"(8) : "memory");
        asm volatile("mbarrier.init.shared.b64 [%0], %1;" :: "r"(mbar_local + 8), "r"(8) : "memory");
    }
    __syncthreads();

    // loc staging ownership (tid < 160): u32 slot 128+j of batch bl (bf16 pair e=2j,2j+1)
    int bl_st = tid / 10, j_st = tid - bl_st * 10;
    bool stager = (tid < 160);

    // stage loc for step 0 into buffer 0
    if (stager) {
        int s0 = dir ? (nloc - 1) : 0;
        float2 lv = *(const float2*)&g_loc[((size_t)s0 * B + b0 + bl_st) * 20 + 2 * j_st];
        ((unsigned*)(smem + OFF_HT0))[bl_st * HROW + 128 + j_st] = pack_bf16x2(lv.x, lv.y);
    }

    int lane = tid & 31, wid = tid >> 5;
    int g = lane >> 2, t = lane & 3;
    int m = wid & 7, n = wid >> 3;

    // epilogue ownership: 1 cell per thread (hl 0..31, b2 0..15)
    int hl = tid & 31, b2 = tid >> 5;
    int bme = b0 + b2;
    int mylen = len[bme];
    float c_reg = 0.0f, h_reg = 0.0f;

    // remote DSMEM addrs (even-hl threads): u32 slot of bf16 pair (kme, kme+1), base hT0
    unsigned rem[8];
    {
        int kme = gx * 32 + hl;
        unsigned char* dst = smem + OFF_HT0 + (b2 * HROW + (kme >> 1)) * 4;
        unsigned lcl;
        asm("{ .reg .u64 tt; cvta.to.shared.u64 tt, %1; cvt.u32.u64 %0, tt; }"
            : "=r"(lcl) : "l"((void*)dst));
        #pragma unroll
        for (int r = 0; r < 8; r++)
            asm("mapa.shared::cluster.u32 %0, %1, %2;" : "=r"(rem[r]) : "r"(lcl), "r"(r));
    }
    unsigned mbar_peer[2] = {0u, 0u};
    if (tid < 8) {
        asm("mapa.shared::cluster.u32 %0, %1, %2;" : "=r"(mbar_peer[0]) : "r"(mbar_local), "r"(tid));
        mbar_peer[1] = mbar_peer[0] + 8;
    }

    // cluster-wide: smem + mbarriers initialized before any DSMEM traffic
    asm volatile("barrier.cluster.arrive.aligned;" ::: "memory");
    asm volatile("barrier.cluster.wait.aligned;"   ::: "memory");

    for (int i = 0; i < nloc; i++) {
        int cur = i & 1;
        const unsigned* hC = (const unsigned*)(smem + (cur ? OFF_HT1 : OFF_HT0));
        unsigned* hN = (unsigned*)(smem + (cur ? OFF_HT0 : OFF_HT1));
        int s = dir ? (nloc - 1 - i) : i;

        // prefetch next step's loc slice (independent of recurrence) BEFORE the wait
        unsigned stage_val = 0u;
        bool do_stage = stager && (i + 1 < nloc);
        if (do_stage) {
            int s_next = dir ? (nloc - 2 - i) : (i + 1);
            float2 lv = *(const float2*)&g_loc[((size_t)s_next * B + b0 + bl_st) * 20 + 2 * j_st];
            stage_val = pack_bf16x2(lv.x, lv.y);
        }

        // wait for step-i h buffer (peers' epilogue of step i-1)
        if (i > 0) {
            unsigned mb = mbar_local + (unsigned)(cur * 8);
            unsigned parity = ((i - 1) >> 1) & 1;
            unsigned done;
            do {
                asm volatile(
                    "{\n\t.reg .pred p;\n\t"
                    "mbarrier.try_wait.parity.acquire.cluster.shared::cta.b64 p, [%1], %2, 0x989680;\n\t"
                    "selp.b32 %0, 1, 0, p;\n\t}"
                    : "=r"(done) : "r"(mb), "r"(parity) : "memory");
            } while (!done);
        }

        // store staged loc into the NEXT buffer (its prior readers finished last step)
        if (do_stage) hN[bl_st * HROW + 128 + j_st] = stage_val;

        // GEMM: 18 k-steps m16n8k16 bf16; A = W frags (LDS.128), B = packed rows (LDS.32)
        float c0[4] = {0.f, 0.f, 0.f, 0.f}, c1[4] = {0.f, 0.f, 0.f, 0.f};
        {
            const uint4* ap = reinterpret_cast<const uint4*>(smem) + m * (KS * 32) + lane;
            const unsigned* hb = hC + (n * 8 + g) * HROW + t;
            #pragma unroll
            for (int ks = 0; ks < KS; ks += 2) {
                uint4 a0 = ap[ks * 32];
                mma_bf16(c0, a0, hb[ks * 8], hb[ks * 8 + 4]);
                uint4 a1 = ap[(ks + 1) * 32];
                mma_bf16(c1, a1, hb[(ks + 1) * 8], hb[(ks + 1) * 8 + 4]);
            }
        }
        {
            int bl = n * 8 + 2 * t;
            *(float2*)&pre[(m * 16 + g) * 20 + bl]     = make_float2(c0[0] + c1[0], c0[1] + c1[1]);
            *(float2*)&pre[(m * 16 + g + 8) * 20 + bl] = make_float2(c0[2] + c1[2], c0[3] + c1[3]);
        }
        __syncthreads();

        // epilogue: 1 cell per thread; pair-pack bf16, even threads broadcast u32
        if (s < mylen) {
            float gi = pre[(4 * hl + 0) * 20 + b2];
            float gf = pre[(4 * hl + 1) * 20 + b2];
            float gg = pre[(4 * hl + 2) * 20 + b2];
            float go = pre[(4 * hl + 3) * 20 + b2];
            float cn = sigm(gf) * c_reg + sigm(gi) * tanh_fast(gg);
            c_reg = cn;
            h_reg = sigm(go) * tanh_fast(cn);
            g_hstore[(((size_t)dir * T + s) * B + bme) * H + gx * 32 + hl] = h_reg;
        }
        {
            unsigned hv = pack_bf16x2(h_reg, 0.f) & 0xffffu;       // own bf16 in low half
            unsigned pv = __shfl_xor_sync(0xffffffffu, hv, 1);     // partner's bf16
            if ((hl & 1) == 0) {
                unsigned packed = hv | (pv << 16);
                unsigned boff = cur ? 0u : (unsigned)HT_BYTES;     // target hN = other buffer
                #pragma unroll
                for (int r = 0; r < 8; r++) {
                    asm volatile("st.shared::cluster.b32 [%0], %1;"
                                 :: "r"(rem[r] + boff), "r"(packed) : "memory");
                }
            }
        }
        __syncthreads();
        // signal buffer (i+1)&1 full: one release-arrive per peer from tids 0-7
        if (tid < 8) {
            unsigned mb = mbar_peer[(i + 1) & 1];
            asm volatile("mbarrier.arrive.release.cluster.shared::cluster.b64 _, [%0];"
                         :: "r"(mb) : "memory");
        }
    }

    // DSMEM lifetime: no CTA exits while peers may still touch its smem
    asm volatile("barrier.cluster.arrive.aligned;" ::: "memory");
    asm volatile("barrier.cluster.wait.aligned;"   ::: "memory");
}

// ------------------- scores: comb_W . tanh(out_W @ [hf;hb] + addr_feat) -------------------
__global__ void __launch_bounds__(256) score_kernel(const int* __restrict__ len,
                                                    const float* __restrict__ comb_W) {
    int b = blockIdx.y;
    int t0 = blockIdx.x * 8;
    int n = len[b];
    if (t0 >= n) return;
    int w = threadIdx.x >> 5, lane = threadIdx.x & 31;
    int t = t0 + w;
    if (t >= n) return;
    float a0 = g_af[b * 32 + lane], a1 = 0.f, a2 = 0.f, a3 = 0.f;
    const float* hf = &g_hstore[(((size_t)0 * T + t) * B + b) * H];
    const float* hb = &g_hstore[(((size_t)1 * T + t) * B + b) * H];
    #pragma unroll 8
    for (int k = 0; k < 256; k += 4) {
        float4 h4 = *(const float4*)&hf[k];
        a0 = fmaf(g_outWT[(k + 0) * 32 + lane], h4.x, a0);
        a1 = fmaf(g_outWT[(k + 1) * 32 + lane], h4.y, a1);
        a2 = fmaf(g_outWT[(k + 2) * 32 + lane], h4.z, a2);
        a3 = fmaf(g_outWT[(k + 3) * 32 + lane], h4.w, a3);
    }
    #pragma unroll 8
    for (int k = 0; k < 256; k += 4) {
        float4 h4 = *(const float4*)&hb[k];
        a0 = fmaf(g_outWT[(256 + k + 0) * 32 + lane], h4.x, a0);
        a1 = fmaf(g_outWT[(256 + k + 1) * 32 + lane], h4.y, a1);
        a2 = fmaf(g_outWT[(256 + k + 2) * 32 + lane], h4.z, a2);
        a3 = fmaf(g_outWT[(256 + k + 3) * 32 + lane], h4.w, a3);
    }
    float v = tanhf(a0 + a1 + a2 + a3) * comb_W[lane];
    #pragma unroll
    for (int off = 16; off; off >>= 1) v += __shfl_down_sync(0xffffffffu, v, off);
    if (lane == 0) g_scores[b * T + t] = v;
}

// ------------------- masked log-softmax over T -------------------
__global__ void __launch_bounds__(256) softmax_kernel(const int* __restrict__ len,
                                                      float* __restrict__ out) {
    int b = blockIdx.x;
    int n = len[b];
    int tid = threadIdx.x;
    __shared__ float red[256];
    float m = -1e30f;
    for (int t = tid; t < n; t += 256) m = fmaxf(m, g_scores[b * T + t]);
    red[tid] = m; __syncthreads();
    for (int st = 128; st; st >>= 1) {
        if (tid < st) red[tid] = fmaxf(red[tid], red[tid + st]);
        __syncthreads();
    }
    m = red[0]; __syncthreads();
    float sum = 0.f;
    for (int t = tid; t < n; t += 256) sum += expf(g_scores[b * T + t] - m);
    red[tid] = sum; __syncthreads();
    for (int st = 128; st; st >>= 1) {
        if (tid < st) red[tid] += red[tid + st];
        __syncthreads();
    }
    float lse = m + logf(red[0]);
    for (int t = tid; t < T; t += 256)
        out[b * T + t] = (t < n) ? (g_scores[b * T + t] - lse) : 0.0f;
}

// ------------------- launch -------------------
extern "C" void kernel_launch(void* const* d_in, const int* in_sizes, int n_in,
                              void* d_out, int out_size) {
    (void)in_sizes; (void)n_in; (void)out_size;
    const float* addr      = (const float*)d_in[0];
    const int*   addr_type = (const int*)  d_in[1];
    const float* loc_dense = (const float*)d_in[2];
    const float* time_dist = (const float*)d_in[3];
    const int*   len       = (const int*)  d_in[4];
    const float* poi_emb   = (const float*)d_in[5];
    const float* time_W    = (const float*)d_in[6];
    const float* time_b    = (const float*)d_in[7];
    const float* addr_W    = (const float*)d_in[8];
    const float* addr_b    = (const float*)d_in[9];
    const float* Wih_f     = (const float*)d_in[10];
    const float* Whh_f     = (const float*)d_in[11];
    const float* b_f       = (const float*)d_in[12];
    const float* Wih_b     = (const float*)d_in[13];
    const float* Whh_b     = (const float*)d_in[14];
    const float* b_b       = (const float*)d_in[15];
    const float* out_W     = (const float*)d_in[16];
    const float* comb_W    = (const float*)d_in[17];
    float* out = (float*)d_out;

    static int smem_set = 0;
    if (!smem_set) {
        cudaFuncSetAttribute(lstm_kernel,
                             cudaFuncAttributeMaxDynamicSharedMemorySize, LSTM_SMEM);
        smem_set = 1;
    }

    addr_kernel<<<1, 128>>>(addr, addr_type, poi_emb, addr_W, addr_b);
    prep_kernel<<<1152, 256>>>(Whh_f, Whh_b, Wih_f, b_f, Wih_b, b_b, out_W);
    loc_kernel<<<dim3(64, 128), 320>>>(loc_dense, time_dist, len, time_W, time_b);
    lstm_kernel<<<dim3(8, 8, 2), 512, LSTM_SMEM>>>(len);
    score_kernel<<<dim3(128, 128), 256>>>(len, comb_W);
    softmax_kernel<<<128, 256>>>(len, out);
}

// round 15
// speedup vs baseline: 1.5227x; 1.5227x over previous
#include <cuda_runtime.h>
#include <cuda_bf16.h>
#include <math.h>

#define B 128
#define T 1024
#define H 256
#define KS 18     // bf16 k16 MMA k-steps: K = 288 = 256 h + 20 loc/bias + 12 pad

// ------------------- device scratch (static) -------------------
__device__ float    g_loc[(size_t)T * B * 20];       // [t][b][20]: loc_dense(16) + td(3) + 1.0
__device__ float    g_hstore[(size_t)2 * T * B * H]; // recorded h (fp32), [d][t][b][h]
__device__ unsigned g_WB[2 * 8 * 8 * KS * 32 * 4];   // fused [Whh|Wih|b] bf16 A-frags (bf16x2/u32)
__device__ float    g_outWT[512 * 32];               // out_W transposed: [k][j]
__device__ float    g_af[B * 32];                    // addr_feat
__device__ float    g_scores[B * T];

__device__ __forceinline__ float tanh_fast(float x) {
    float r;
    asm("tanh.approx.f32 %0, %1;" : "=f"(r) : "f"(x));
    return r;
}
__device__ __forceinline__ float sigm(float x) {
    return fmaf(0.5f, tanh_fast(0.5f * x), 0.5f);
}
__device__ __forceinline__ void mma_bf16(float c[4], uint4 a, unsigned b0, unsigned b1) {
    asm volatile("mma.sync.aligned.m16n8k16.row.col.f32.bf16.bf16.f32 "
                 "{%0,%1,%2,%3}, {%4,%5,%6,%7}, {%8,%9}, {%0,%1,%2,%3};"
                 : "+f"(c[0]), "+f"(c[1]), "+f"(c[2]), "+f"(c[3])
                 : "r"(a.x), "r"(a.y), "r"(a.z), "r"(a.w), "r"(b0), "r"(b1));
}
__device__ __forceinline__ unsigned pack_bf16x2(float lo, float hi) {
    unsigned u;
    asm("cvt.rn.bf16x2.f32 %0, %1, %2;" : "=r"(u) : "f"(hi), "f"(lo));
    return u;
}

// smem layout (bytes)
#define WF_BYTES  73728                  // 8 m x 18 ks x 32 lane x 4 u32
#define HROW      148                    // u32 per B row (296 bf16; (20g+t)%32 distinct -> conflict-free)
#define HT_BYTES  (16 * HROW * 4)        // 9472
#define OFF_HT0   WF_BYTES
#define OFF_HT1   (OFF_HT0 + HT_BYTES)
#define OFF_PRE   (OFF_HT1 + HT_BYTES)
#define OFF_MBAR  (OFF_PRE + 128 * 20 * 4)
#define LSTM_SMEM 118784                 // padded so each CTA owns an SM

// ------------------- weight prep: fused bf16 A-fragments + outWT -------------------
__global__ void prep_kernel(const float* __restrict__ Whh_f, const float* __restrict__ Whh_b,
                            const float* __restrict__ Wih_f, const float* __restrict__ b_f,
                            const float* __restrict__ Wih_b, const float* __restrict__ b_b,
                            const float* __restrict__ out_W) {
    int idx = blockIdx.x * 256 + threadIdx.x;
    if (idx < 2 * 8 * 8 * KS * 32 * 4) {
        int r     = idx & 3;
        int lane  = (idx >> 2) & 31;
        int ks    = (idx >> 7) % KS;
        int rest  = (idx >> 7) / KS;
        int m     = rest & 7;
        int gxp   = (rest >> 3) & 7;
        int d     = rest >> 6;
        int g = lane >> 2, t = lane & 3;
        int row_local = g + (r & 1) * 8;
        int kbase = ks * 16 + 2 * t + ((r & 2) ? 8 : 0);
        int rp = gxp * 128 + m * 16 + row_local;   // reordered row r' = 4*jh + gate
        int gate = rp & 3, jh = rp >> 2;
        int orig = gate * 256 + jh;
        float v[2];
        #pragma unroll
        for (int q = 0; q < 2; q++) {
            int k = kbase + q;
            if (k < 256)            v[q] = (d ? Whh_b : Whh_f)[orig * H + k];
            else if (k < 275)       v[q] = (d ? Wih_b : Wih_f)[orig * 19 + (k - 256)];
            else if (k == 275)      v[q] = (d ? b_b : b_f)[orig];
            else                    v[q] = 0.0f;
        }
        g_WB[idx] = pack_bf16x2(v[0], v[1]);
    }
    if (idx < 512 * 32) {
        int k = idx >> 5, j = idx & 31;
        g_outWT[idx] = out_W[j * 512 + k];
    }
}

// ------------------- addr_feat -------------------
__global__ void addr_kernel(const float* __restrict__ addr,
                            const int*   __restrict__ addr_type,
                            const float* __restrict__ poi_emb,
                            const float* __restrict__ addr_W,
                            const float* __restrict__ addr_b) {
    int b = threadIdx.x;  // 128
    float inp[4];
    inp[0] = addr[b];
    int at = addr_type[b];
    inp[1] = poi_emb[at * 3 + 0];
    inp[2] = poi_emb[at * 3 + 1];
    inp[3] = poi_emb[at * 3 + 2];
    for (int j = 0; j < 32; j++) {
        float a = addr_b[j];
        #pragma unroll
        for (int f = 0; f < 4; f++) a += addr_W[j * 4 + f] * inp[f];
        g_af[b * 32 + j] = a;
    }
}

// ------------------- loc_kernel: g_loc[t][b][20] = [loc_dense | td | 1], active only -------------------
__global__ void __launch_bounds__(320) loc_kernel(
    const float* __restrict__ loc_dense, const float* __restrict__ time_dist,
    const int* __restrict__ len, const float* __restrict__ time_W,
    const float* __restrict__ time_b) {
    int b = blockIdx.y;
    int t0 = blockIdx.x * 16;
    int n = len[b];
    if (t0 >= n) return;
    int tid = threadIdx.x;
    int tt = tid / 20, e = tid - tt * 20;
    int t = t0 + tt;
    if (t >= n) return;
    float v;
    if (e < 16) {
        v = loc_dense[((size_t)b * T + t) * 16 + e];
    } else if (e < 19) {
        int w = e - 16;
        float acc = time_b[w];
        const float* tdp = &time_dist[((size_t)b * T + t) * 8];
        #pragma unroll
        for (int f = 0; f < 8; f++) acc += time_W[w * 8 + f] * tdp[f];
        v = acc;
    } else {
        v = 1.0f;   // bias lane
    }
    g_loc[((size_t)t * B + b) * 20 + e] = v;
}

// ------------------- persistent bidirectional LSTM: fused-K bf16 MMA + mbarrier DSMEM sync ------------
// Grid (8,8,2), cluster (8,1,1) = 8 gate-tile CTAs sharing (btile, dir).
// gates[128 rows][16 b] = [Whh|Wih|b] (bf16 A frags) x [h; loc; 1] (bf16 B rows, u32-packed pairs).
// K = 288: k<256 = h (DSMEM-exchanged as bf16x2 u32), k 256..275 = loc+bias, rest zero pad.
// Exchange: shuffle-pair pack, even threads issue 8 remote u32 stores (2048/CTA/step).
// Sync identical to R10/R13: 2 block syncs, count=8 double-buffered mbarriers, tids 0-7 arrive.
__global__ void __launch_bounds__(512, 1) __cluster_dims__(8, 1, 1)
lstm_kernel(const int* __restrict__ len) {
    extern __shared__ __align__(16) unsigned char smem[];
    float* pre = (float*)(smem + OFF_PRE);           // [128 rows][20 b]

    int gx  = blockIdx.x;   // gate tile == cluster rank
    int gy  = blockIdx.y;
    int dir = blockIdx.z;
    int tid = threadIdx.x;
    int b0  = gy * 16;
    int nloc = len[b0];     // sorted descending -> tile max (same for whole cluster)

    unsigned mbar_local;
    asm("{ .reg .u64 tt; cvta.to.shared.u64 tt, %1; cvt.u32.u64 %0, tt; }"
        : "=r"(mbar_local) : "l"((void*)(smem + OFF_MBAR)));

    // resident fused weight fragments (72 KB)
    {
        const uint4* Wf = reinterpret_cast<const uint4*>(g_WB) + (size_t)(dir * 8 + gx) * 4608;
        uint4* dst = reinterpret_cast<uint4*>(smem);
        for (int e = tid; e < 4608; e += 512) dst[e] = Wf[e];
    }
    // zero BOTH h buffers (incl. pad k-region, never rewritten)
    for (int e = tid; e < 2 * HT_BYTES / 4; e += 512) ((unsigned*)(smem + OFF_HT0))[e] = 0u;
    if (tid == 0) {
        asm volatile("mbarrier.init.shared.b64 [%0], %1;" :: "r"(mbar_local), "r"(8) : "memory");
        asm volatile("mbarrier.init.shared.b64 [%0], %1;" :: "r"(mbar_local + 8), "r"(8) : "memory");
    }
    __syncthreads();

    // loc staging ownership (tid < 160): u32 slot 128+j of batch bl (bf16 pair e=2j,2j+1)
    int bl_st = tid / 10, j_st = tid - bl_st * 10;
    bool stager = (tid < 160);

    // stage loc for step 0 into buffer 0
    if (stager) {
        int s0 = dir ? (nloc - 1) : 0;
        float2 lv = *(const float2*)&g_loc[((size_t)s0 * B + b0 + bl_st) * 20 + 2 * j_st];
        ((unsigned*)(smem + OFF_HT0))[bl_st * HROW + 128 + j_st] = pack_bf16x2(lv.x, lv.y);
    }

    int lane = tid & 31, wid = tid >> 5;
    int g = lane >> 2, t = lane & 3;
    int m = wid & 7, n = wid >> 3;

    // epilogue ownership: 1 cell per thread (hl 0..31, b2 0..15)
    int hl = tid & 31, b2 = tid >> 5;
    int bme = b0 + b2;
    int mylen = len[bme];
    float c_reg = 0.0f, h_reg = 0.0f;

    // remote DSMEM addrs (even-hl threads): u32 slot of bf16 pair (kme, kme+1), base hT0
    unsigned rem[8];
    {
        int kme = gx * 32 + hl;
        unsigned char* dst = smem + OFF_HT0 + (b2 * HROW + (kme >> 1)) * 4;
        unsigned lcl;
        asm("{ .reg .u64 tt; cvta.to.shared.u64 tt, %1; cvt.u32.u64 %0, tt; }"
            : "=r"(lcl) : "l"((void*)dst));
        #pragma unroll
        for (int r = 0; r < 8; r++)
            asm("mapa.shared::cluster.u32 %0, %1, %2;" : "=r"(rem[r]) : "r"(lcl), "r"(r));
    }
    unsigned mbar_peer[2] = {0u, 0u};
    if (tid < 8) {
        asm("mapa.shared::cluster.u32 %0, %1, %2;" : "=r"(mbar_peer[0]) : "r"(mbar_local), "r"(tid));
        mbar_peer[1] = mbar_peer[0] + 8;
    }

    // cluster-wide: smem + mbarriers initialized before any DSMEM traffic
    asm volatile("barrier.cluster.arrive.aligned;" ::: "memory");
    asm volatile("barrier.cluster.wait.aligned;"   ::: "memory");

    for (int i = 0; i < nloc; i++) {
        int cur = i & 1;
        const unsigned* hC = (const unsigned*)(smem + (cur ? OFF_HT1 : OFF_HT0));
        unsigned* hN = (unsigned*)(smem + (cur ? OFF_HT0 : OFF_HT1));
        int s = dir ? (nloc - 1 - i) : i;

        // prefetch next step's loc slice (independent of recurrence) BEFORE the wait
        unsigned stage_val = 0u;
        bool do_stage = stager && (i + 1 < nloc);
        if (do_stage) {
            int s_next = dir ? (nloc - 2 - i) : (i + 1);
            float2 lv = *(const float2*)&g_loc[((size_t)s_next * B + b0 + bl_st) * 20 + 2 * j_st];
            stage_val = pack_bf16x2(lv.x, lv.y);
        }

        // wait for step-i h buffer (peers' epilogue of step i-1)
        if (i > 0) {
            unsigned mb = mbar_local + (unsigned)(cur * 8);
            unsigned parity = ((i - 1) >> 1) & 1;
            unsigned done;
            do {
                asm volatile(
                    "{\n\t.reg .pred p;\n\t"
                    "mbarrier.try_wait.parity.acquire.cluster.shared::cta.b64 p, [%1], %2, 0x989680;\n\t"
                    "selp.b32 %0, 1, 0, p;\n\t}"
                    : "=r"(done) : "r"(mb), "r"(parity) : "memory");
            } while (!done);
        }

        // store staged loc into the NEXT buffer (its prior readers finished last step)
        if (do_stage) hN[bl_st * HROW + 128 + j_st] = stage_val;

        // GEMM: 18 k-steps m16n8k16 bf16; A = W frags (LDS.128), B = packed rows (LDS.32)
        float c0[4] = {0.f, 0.f, 0.f, 0.f}, c1[4] = {0.f, 0.f, 0.f, 0.f};
        {
            const uint4* ap = reinterpret_cast<const uint4*>(smem) + m * (KS * 32) + lane;
            const unsigned* hb = hC + (n * 8 + g) * HROW + t;
            #pragma unroll
            for (int ks = 0; ks < KS; ks += 2) {
                uint4 a0 = ap[ks * 32];
                mma_bf16(c0, a0, hb[ks * 8], hb[ks * 8 + 4]);
                uint4 a1 = ap[(ks + 1) * 32];
                mma_bf16(c1, a1, hb[(ks + 1) * 8], hb[(ks + 1) * 8 + 4]);
            }
        }
        {
            int bl = n * 8 + 2 * t;
            *(float2*)&pre[(m * 16 + g) * 20 + bl]     = make_float2(c0[0] + c1[0], c0[1] + c1[1]);
            *(float2*)&pre[(m * 16 + g + 8) * 20 + bl] = make_float2(c0[2] + c1[2], c0[3] + c1[3]);
        }
        __syncthreads();

        // epilogue: 1 cell per thread; pair-pack bf16, even threads broadcast u32
        if (s < mylen) {
            float gi = pre[(4 * hl + 0) * 20 + b2];
            float gf = pre[(4 * hl + 1) * 20 + b2];
            float gg = pre[(4 * hl + 2) * 20 + b2];
            float go = pre[(4 * hl + 3) * 20 + b2];
            float cn = sigm(gf) * c_reg + sigm(gi) * tanh_fast(gg);
            c_reg = cn;
            h_reg = sigm(go) * tanh_fast(cn);
            g_hstore[(((size_t)dir * T + s) * B + bme) * H + gx * 32 + hl] = h_reg;
        }
        {
            unsigned hv = pack_bf16x2(h_reg, 0.f) & 0xffffu;       // own bf16 in low half
            unsigned pv = __shfl_xor_sync(0xffffffffu, hv, 1);     // partner's bf16
            if ((hl & 1) == 0) {
                unsigned packed = hv | (pv << 16);
                unsigned boff = cur ? 0u : (unsigned)HT_BYTES;     // target hN = other buffer
                #pragma unroll
                for (int r = 0; r < 8; r++) {
                    asm volatile("st.shared::cluster.b32 [%0], %1;"
                                 :: "r"(rem[r] + boff), "r"(packed) : "memory");
                }
            }
        }
        __syncthreads();
        // signal buffer (i+1)&1 full: one release-arrive per peer from tids 0-7
        if (tid < 8) {
            unsigned mb = mbar_peer[(i + 1) & 1];
            asm volatile("mbarrier.arrive.release.cluster.shared::cluster.b64 _, [%0];"
                         :: "r"(mb) : "memory");
        }
    }

    // DSMEM lifetime: no CTA exits while peers may still touch its smem
    asm volatile("barrier.cluster.arrive.aligned;" ::: "memory");
    asm volatile("barrier.cluster.wait.aligned;"   ::: "memory");
}

// ------------------- scores: comb_W . tanh(out_W @ [hf;hb] + addr_feat) -------------------
__global__ void __launch_bounds__(256) score_kernel(const int* __restrict__ len,
                                                    const float* __restrict__ comb_W) {
    int b = blockIdx.y;
    int t0 = blockIdx.x * 8;
    int n = len[b];
    if (t0 >= n) return;
    int w = threadIdx.x >> 5, lane = threadIdx.x & 31;
    int t = t0 + w;
    if (t >= n) return;
    float a0 = g_af[b * 32 + lane], a1 = 0.f, a2 = 0.f, a3 = 0.f;
    const float* hf = &g_hstore[(((size_t)0 * T + t) * B + b) * H];
    const float* hb = &g_hstore[(((size_t)1 * T + t) * B + b) * H];
    #pragma unroll 8
    for (int k = 0; k < 256; k += 4) {
        float4 h4 = *(const float4*)&hf[k];
        a0 = fmaf(g_outWT[(k + 0) * 32 + lane], h4.x, a0);
        a1 = fmaf(g_outWT[(k + 1) * 32 + lane], h4.y, a1);
        a2 = fmaf(g_outWT[(k + 2) * 32 + lane], h4.z, a2);
        a3 = fmaf(g_outWT[(k + 3) * 32 + lane], h4.w, a3);
    }
    #pragma unroll 8
    for (int k = 0; k < 256; k += 4) {
        float4 h4 = *(const float4*)&hb[k];
        a0 = fmaf(g_outWT[(256 + k + 0) * 32 + lane], h4.x, a0);
        a1 = fmaf(g_outWT[(256 + k + 1) * 32 + lane], h4.y, a1);
        a2 = fmaf(g_outWT[(256 + k + 2) * 32 + lane], h4.z, a2);
        a3 = fmaf(g_outWT[(256 + k + 3) * 32 + lane], h4.w, a3);
    }
    float v = tanhf(a0 + a1 + a2 + a3) * comb_W[lane];
    #pragma unroll
    for (int off = 16; off; off >>= 1) v += __shfl_down_sync(0xffffffffu, v, off);
    if (lane == 0) g_scores[b * T + t] = v;
}

// ------------------- masked log-softmax over T -------------------
__global__ void __launch_bounds__(256) softmax_kernel(const int* __restrict__ len,
                                                      float* __restrict__ out) {
    int b = blockIdx.x;
    int n = len[b];
    int tid = threadIdx.x;
    __shared__ float red[256];
    float m = -1e30f;
    for (int t = tid; t < n; t += 256) m = fmaxf(m, g_scores[b * T + t]);
    red[tid] = m; __syncthreads();
    for (int st = 128; st; st >>= 1) {
        if (tid < st) red[tid] = fmaxf(red[tid], red[tid + st]);
        __syncthreads();
    }
    m = red[0]; __syncthreads();
    float sum = 0.f;
    for (int t = tid; t < n; t += 256) sum += expf(g_scores[b * T + t] - m);
    red[tid] = sum; __syncthreads();
    for (int st = 128; st; st >>= 1) {
        if (tid < st) red[tid] += red[tid + st];
        __syncthreads();
    }
    float lse = m + logf(red[0]);
    for (int t = tid; t < T; t += 256)
        out[b * T + t] = (t < n) ? (g_scores[b * T + t] - lse) : 0.0f;
}

// ------------------- launch -------------------
extern "C" void kernel_launch(void* const* d_in, const int* in_sizes, int n_in,
                              void* d_out, int out_size) {
    (void)in_sizes; (void)n_in; (void)out_size;
    const float* addr      = (const float*)d_in[0];
    const int*   addr_type = (const int*)  d_in[1];
    const float* loc_dense = (const float*)d_in[2];
    const float* time_dist = (const float*)d_in[3];
    const int*   len       = (const int*)  d_in[4];
    const float* poi_emb   = (const float*)d_in[5];
    const float* time_W    = (const float*)d_in[6];
    const float* time_b    = (const float*)d_in[7];
    const float* addr_W    = (const float*)d_in[8];
    const float* addr_b    = (const float*)d_in[9];
    const float* Wih_f     = (const float*)d_in[10];
    const float* Whh_f     = (const float*)d_in[11];
    const float* b_f       = (const float*)d_in[12];
    const float* Wih_b     = (const float*)d_in[13];
    const float* Whh_b     = (const float*)d_in[14];
    const float* b_b       = (const float*)d_in[15];
    const float* out_W     = (const float*)d_in[16];
    const float* comb_W    = (const float*)d_in[17];
    float* out = (float*)d_out;

    static int smem_set = 0;
    if (!smem_set) {
        cudaFuncSetAttribute(lstm_kernel,
                             cudaFuncAttributeMaxDynamicSharedMemorySize, LSTM_SMEM);
        smem_set = 1;
    }

    addr_kernel<<<1, 128>>>(addr, addr_type, poi_emb, addr_W, addr_b);
    prep_kernel<<<1152, 256>>>(Whh_f, Whh_b, Wih_f, b_f, Wih_b, b_b, out_W);
    loc_kernel<<<dim3(64, 128), 320>>>(loc_dense, time_dist, len, time_W, time_b);
    lstm_kernel<<<dim3(8, 8, 2), 512, LSTM_SMEM>>>(len);
    score_kernel<<<dim3(128, 128), 256>>>(len, comb_W);
    softmax_kernel<<<128, 256>>>(len, out);
}